// round 10
// baseline (speedup 1.0000x reference)
#include <cuda_runtime.h>
#include <cuda_bf16.h>
#include <cstdint>
#include <math.h>

#define B_   2
#define S_   2048
#define HID_ 3072
#define NH_  16
#define NKV_ 8
#define HD_  256
#define NREP_ 2

// ---------------- scratch (device globals; no allocation allowed) ----------------
__device__ float g_q [(size_t)B_*NH_ *S_*HD_];   // [B,NH,S,HD] fp32 (pre-rope)
__device__ float g_k [(size_t)B_*NKV_*S_*HD_];   // [B,NKV,S,HD] fp32 (pre-rope)
__device__ float g_v [(size_t)B_*NKV_*S_*HD_];   // [B,NKV,S,HD] fp32
__device__ float g_o [(size_t)B_*S_*NH_*HD_];    // [B,S,NH*HD] fp32

__device__ __nv_bfloat16 g_qh[(size_t)B_*NH_ *S_*HD_];  // Q hi limb [B,NH,S,HD]
__device__ __nv_bfloat16 g_ql[(size_t)B_*NH_ *S_*HD_];  // Q lo limb
__device__ __nv_bfloat16 g_kq[(size_t)B_*NKV_*S_*HD_];  // quantized K (exact bf16) [B,NKV,S,HD]
__device__ __nv_bfloat16 g_vh[(size_t)B_*NKV_*HD_*S_];  // V hi limb, d-major [B,NKV,HD,S]
__device__ __nv_bfloat16 g_vl[(size_t)B_*NKV_*HD_*S_];  // V lo limb, d-major

// ================= tensor-core helpers =================
__device__ __forceinline__ uint32_t s2u(const void* p) {
    return (uint32_t)__cvta_generic_to_shared(p);
}

#define LDSM4(r, addr)                                                          \
    asm volatile("ldmatrix.sync.aligned.m8n8.x4.shared.b16 {%0,%1,%2,%3}, [%4];"\
                 : "=r"((r)[0]), "=r"((r)[1]), "=r"((r)[2]), "=r"((r)[3])       \
                 : "r"(addr))

#define MMA_BF16(c, a, b0, b1)                                                  \
    asm volatile("mma.sync.aligned.m16n8k16.row.col.f32.bf16.bf16.f32 "         \
                 "{%0,%1,%2,%3}, {%4,%5,%6,%7}, {%8,%9}, {%0,%1,%2,%3};"        \
                 : "+f"((c)[0]), "+f"((c)[1]), "+f"((c)[2]), "+f"((c)[3])       \
                 : "r"((a)[0]), "r"((a)[1]), "r"((a)[2]), "r"((a)[3]),          \
                   "r"(b0), "r"(b1))

__device__ __forceinline__ uint32_t packbf(__nv_bfloat16 a, __nv_bfloat16 b) {
    return (uint32_t)__bfloat16_as_ushort(a) | ((uint32_t)__bfloat16_as_ushort(b) << 16);
}

__device__ __forceinline__ void split2(float x0, float x1, uint32_t* p) {
    __nv_bfloat16 h0 = __float2bfloat16(x0);
    __nv_bfloat16 h1 = __float2bfloat16(x1);
    p[0] = packbf(h0, h1);
    float r0 = x0 - __bfloat162float(h0);
    float r1 = x1 - __bfloat162float(h1);
    p[1] = packbf(__float2bfloat16(r0), __float2bfloat16(r1));
}

// ================= fp32 NT SGEMM device body (K projection — DO NOT ALTER OPS) ======
// Identical FFMA sequence to the proven standalone kernel; smem is caller-provided.
template<int MODE>
__device__ void gemm_nt_dev(char* fsm, int bx, int by,
                            const float* __restrict__ A, const float* __restrict__ W,
                            float* __restrict__ C, int M, int N, int K, int H)
{
    float (*As)[132] = reinterpret_cast<float(*)[132]>(fsm);
    float (*Bs)[132] = reinterpret_cast<float(*)[132]>(fsm + 16*132*sizeof(float));
    const int tid = threadIdx.x;
    const int tx = tid & 15, ty = tid >> 4;
    const int m0 = by * 128, n0 = bx * 128;
    const int lr = tid >> 2;
    const int lk = (tid & 3) << 2;

    const float* Ap  = A + (size_t)(m0 + lr) * K + lk;
    const float* Ap2 = Ap + (size_t)64 * K;
    const float* Wp  = W + (size_t)(n0 + lr) * K + lk;
    const float* Wp2 = Wp + (size_t)64 * K;

    float acc[8][8];
#pragma unroll
    for (int i = 0; i < 8; i++)
#pragma unroll
        for (int j = 0; j < 8; j++) acc[i][j] = 0.f;

    for (int k0 = 0; k0 < K; k0 += 16) {
        float4 a0 = *(const float4*)(Ap  + k0);
        float4 a1 = *(const float4*)(Ap2 + k0);
        float4 w0 = *(const float4*)(Wp  + k0);
        float4 w1 = *(const float4*)(Wp2 + k0);
        __syncthreads();
        As[lk+0][lr]    = a0.x; As[lk+1][lr]    = a0.y; As[lk+2][lr]    = a0.z; As[lk+3][lr]    = a0.w;
        As[lk+0][lr+64] = a1.x; As[lk+1][lr+64] = a1.y; As[lk+2][lr+64] = a1.z; As[lk+3][lr+64] = a1.w;
        Bs[lk+0][lr]    = w0.x; Bs[lk+1][lr]    = w0.y; Bs[lk+2][lr]    = w0.z; Bs[lk+3][lr]    = w0.w;
        Bs[lk+0][lr+64] = w1.x; Bs[lk+1][lr+64] = w1.y; Bs[lk+2][lr+64] = w1.z; Bs[lk+3][lr+64] = w1.w;
        __syncthreads();
#pragma unroll
        for (int kk = 0; kk < 16; kk++) {
            float4 fa0 = *(const float4*)&As[kk][ty*4];
            float4 fa1 = *(const float4*)&As[kk][ty*4+64];
            float4 fb0 = *(const float4*)&Bs[kk][tx*4];
            float4 fb1 = *(const float4*)&Bs[kk][tx*4+64];
            float av[8] = {fa0.x,fa0.y,fa0.z,fa0.w, fa1.x,fa1.y,fa1.z,fa1.w};
            float bv[8] = {fb0.x,fb0.y,fb0.z,fb0.w, fb1.x,fb1.y,fb1.z,fb1.w};
#pragma unroll
            for (int i = 0; i < 8; i++)
#pragma unroll
                for (int j = 0; j < 8; j++) acc[i][j] += av[i]*bv[j];
        }
    }

#pragma unroll
    for (int i = 0; i < 8; i++) {
        int row = m0 + ty*4 + (i & 3) + (i >> 2) * 64;
#pragma unroll
        for (int jh = 0; jh < 2; jh++) {
            int col = n0 + tx*4 + jh*64;
            float4 vout = make_float4(acc[i][jh*4+0], acc[i][jh*4+1],
                                      acc[i][jh*4+2], acc[i][jh*4+3]);
            if (MODE == 0) {
                *(float4*)(C + (size_t)row * N + col) = vout;
            } else {
                int b = row >> 11, s = row & (S_-1);
                int h = col >> 8,  hd = col & (HD_-1);
                *(float4*)(C + (((size_t)(b*H + h) * S_ + s) * HD_ + hd)) = vout;
            }
        }
    }
}

// ======== 2-limb bf16 tensor-core NT GEMM device body, double-buffered ========
template<int MODE>
__device__ void gemm_mma2_dev(__nv_bfloat16* dsm, int bx, int by,
                              const float* __restrict__ A, const float* __restrict__ W,
                              float* __restrict__ C, int M, int N, int K, int H)
{
    auto tile = [&](int t) -> __nv_bfloat16 (*)[40] {
        return reinterpret_cast<__nv_bfloat16 (*)[40]>(dsm + (size_t)t * 128 * 40);
    };

    const int tid  = threadIdx.x;
    const int lane = tid & 31, wid = tid >> 5;
    const int wm = wid >> 2;
    const int wn = wid & 3;
    const int m0 = by * 128, n0 = bx * 128;

    const int lr = tid >> 1;
    const int lc = (tid & 1) << 4;

    const float* Ap = A + (size_t)(m0 + lr) * K + lc;
    const float* Wp = W + (size_t)(n0 + lr) * K + lc;

    float acc[4][4][4];
#pragma unroll
    for (int mt = 0; mt < 4; mt++)
#pragma unroll
        for (int nt = 0; nt < 4; nt++)
#pragma unroll
            for (int e = 0; e < 4; e++) acc[mt][nt][e] = 0.f;

    float4 fa[4], fw[4];
#pragma unroll
    for (int i = 0; i < 4; i++) {
        fa[i] = *(const float4*)(Ap + i * 4);
        fw[i] = *(const float4*)(Wp + i * 4);
    }

    auto convert_store = [&](int buf) {
        uint32_t apk[8][2], wpk[8][2];
#pragma unroll
        for (int i = 0; i < 4; i++) {
            split2(fa[i].x, fa[i].y, apk[2*i]);
            split2(fa[i].z, fa[i].w, apk[2*i+1]);
            split2(fw[i].x, fw[i].y, wpk[2*i]);
            split2(fw[i].z, fw[i].w, wpk[2*i+1]);
        }
#pragma unroll
        for (int l = 0; l < 2; l++) {
            __nv_bfloat16 (*sA)[40] = tile(buf*4 + l);
            __nv_bfloat16 (*sB)[40] = tile(buf*4 + 2 + l);
            *(uint4*)&sA[lr][lc]     = make_uint4(apk[0][l], apk[1][l], apk[2][l], apk[3][l]);
            *(uint4*)&sA[lr][lc + 8] = make_uint4(apk[4][l], apk[5][l], apk[6][l], apk[7][l]);
            *(uint4*)&sB[lr][lc]     = make_uint4(wpk[0][l], wpk[1][l], wpk[2][l], wpk[3][l]);
            *(uint4*)&sB[lr][lc + 8] = make_uint4(wpk[4][l], wpk[5][l], wpk[6][l], wpk[7][l]);
        }
    };

    convert_store(0);
    __syncthreads();
    int cur = 0;

    for (int k0 = 0; k0 < K; k0 += 32) {
        const bool more = (k0 + 32 < K);
        if (more) {
#pragma unroll
            for (int i = 0; i < 4; i++) {
                fa[i] = *(const float4*)(Ap + k0 + 32 + i * 4);
                fw[i] = *(const float4*)(Wp + k0 + 32 + i * 4);
            }
        }

#pragma unroll
        for (int ks = 0; ks < 32; ks += 16) {
            uint32_t Bf[2][2][4];
#pragma unroll
            for (int l = 0; l < 2; l++) {
#pragma unroll
                for (int g = 0; g < 2; g++) {
                    const int br = wn * 32 + g * 16 + (lane & 7) + ((lane >> 4) << 3);
                    const int bk = ks + (((lane >> 3) & 1) << 3);
                    LDSM4(Bf[l][g], s2u(&tile(cur*4 + 2 + l)[br][bk]));
                }
            }
#pragma unroll
            for (int mt = 0; mt < 4; mt++) {
                uint32_t Af[2][4];
                const int ar = wm * 64 + mt * 16 + (lane & 15);
                const int ak = ks + ((lane >> 4) << 3);
                LDSM4(Af[0], s2u(&tile(cur*4 + 0)[ar][ak]));
                LDSM4(Af[1], s2u(&tile(cur*4 + 1)[ar][ak]));
#pragma unroll
                for (int nt = 0; nt < 4; nt++) {
                    const int g = nt >> 1, p = (nt & 1) << 1;
                    float* c = acc[mt][nt];
                    MMA_BF16(c, Af[0], Bf[0][g][p], Bf[0][g][p+1]);   // hh
                    MMA_BF16(c, Af[1], Bf[0][g][p], Bf[0][g][p+1]);   // lh
                    MMA_BF16(c, Af[0], Bf[1][g][p], Bf[1][g][p+1]);   // hl
                }
            }
        }

        if (more) convert_store(cur ^ 1);
        __syncthreads();
        cur ^= 1;
    }

#pragma unroll
    for (int mt = 0; mt < 4; mt++) {
        const int row0 = m0 + wm * 64 + mt * 16 + (lane >> 2);
#pragma unroll
        for (int nt = 0; nt < 4; nt++) {
            const int col = n0 + wn * 32 + nt * 8 + ((lane & 3) << 1);
            float2 v0 = make_float2(acc[mt][nt][0], acc[mt][nt][1]);
            float2 v1 = make_float2(acc[mt][nt][2], acc[mt][nt][3]);
            if (MODE == 0) {
                *(float2*)(C + (size_t)row0       * N + col) = v0;
                *(float2*)(C + (size_t)(row0 + 8) * N + col) = v1;
            } else {
                const int h = col >> 8, hd = col & (HD_ - 1);
#pragma unroll
                for (int rr = 0; rr < 2; rr++) {
                    const int row = row0 + rr * 8;
                    const int b = row >> 11, s = row & (S_ - 1);
                    *(float2*)(C + (((size_t)(b * H + h) * S_ + s) * HD_ + hd)) =
                        rr ? v1 : v0;
                }
            }
        }
    }
}

// ======== fused projections: role-specialized CTAs for pipe-level overlap ========
// bid%4: 0,1 -> Q tile (tensor pipe); 2 -> K tile (fp32 FFMA pipe); 3 -> V tile (tensor).
// Ratio 2:1:1 matches tile counts 1024:512:512 exactly; striping mixes roles per SM.
__global__ __launch_bounds__(256)
void proj_fused(const float* __restrict__ hidden,
                const float* __restrict__ Wq, const float* __restrict__ Wk,
                const float* __restrict__ Wv,
                float* __restrict__ q, float* __restrict__ k, float* __restrict__ v)
{
    extern __shared__ char fsm[];
    const int bid = blockIdx.x;
    const int r = bid & 3, g = bid >> 2;
    const int M = B_ * S_;
    if (r < 2) {
        const int qbid = g * 2 + r;                 // 0..1023
        gemm_mma2_dev<1>((__nv_bfloat16*)fsm, qbid & 31, qbid >> 5,
                         hidden, Wq, q, M, NH_*HD_, HID_, NH_);
    } else if (r == 2) {
        gemm_nt_dev<1>(fsm, g & 15, g >> 4,         // 0..511
                       hidden, Wk, k, M, NKV_*HD_, HID_, NKV_);
    } else {
        gemm_mma2_dev<1>((__nv_bfloat16*)fsm, g & 15, g >> 4,
                         hidden, Wv, v, M, NKV_*HD_, HID_, NKV_);
    }
}

// ======== standalone 2-limb GEMM (output projection) ========
template<int MODE>
__global__ __launch_bounds__(256)
void gemm_mma2(const float* __restrict__ A, const float* __restrict__ W,
               float* __restrict__ C, int M, int N, int K, int H)
{
    extern __shared__ __nv_bfloat16 dsm[];
    gemm_mma2_dev<MODE>(dsm, blockIdx.x, blockIdx.y, A, W, C, M, N, K, H);
}

// ---------------- RoPE on Q -> bf16 limbs ----------------
__global__ void rope_q_split(const float* __restrict__ q,
                             __nv_bfloat16* __restrict__ qh,
                             __nv_bfloat16* __restrict__ ql,
                             const float* __restrict__ cosp,
                             const float* __restrict__ sinp)
{
    size_t idx = (size_t)blockIdx.x * blockDim.x + threadIdx.x; // B*NH*S*128
    int d = (int)(idx & 127);
    size_t rrow = idx >> 7;
    int s = (int)(rrow & (S_-1));
    const float* row = q + rrow * HD_;
    float x1 = row[d], x2 = row[d + 128];
    float c1 = cosp[s*HD_ + d],       s1 = sinp[s*HD_ + d];
    float c2 = cosp[s*HD_ + d + 128], s2 = sinp[s*HD_ + d + 128];
    float v1 = x1 * c1 - x2 * s1;
    float v2 = x2 * c2 + x1 * s2;
    __nv_bfloat16 h1 = __float2bfloat16(v1);
    __nv_bfloat16 h2 = __float2bfloat16(v2);
    qh[rrow*HD_ + d]       = h1;
    qh[rrow*HD_ + d + 128] = h2;
    ql[rrow*HD_ + d]       = __float2bfloat16(v1 - __bfloat162float(h1));
    ql[rrow*HD_ + d + 128] = __float2bfloat16(v2 - __bfloat162float(h2));
}

// ------- RoPE + BFP quantize K -> exact bf16, s-major [B,NKV,S,HD] -------
__global__ __launch_bounds__(256)
void rope_quant_k(const float* __restrict__ k, __nv_bfloat16* __restrict__ kq,
                  const float* __restrict__ cosp, const float* __restrict__ sinp)
{
    int r = blockIdx.x;                 // (b*NKV+kv)*S + s
    int s = r & (S_-1);
    int d = threadIdx.x;
    const float* row = k + (size_t)r * HD_;
    float x = row[d];
    float other = (d < 128) ? -row[d + 128] : row[d - 128];
    float val = x * cosp[s*HD_ + d] + other * sinp[s*HD_ + d];

    __shared__ float red[256];
    red[d] = fabsf(val);
    __syncthreads();
    for (int off = 64; off > 0; off >>= 1) {
        if ((d & 127) < off) red[d] = fmaxf(red[d], red[d + off]);
        __syncthreads();
    }
    float maxabs = red[(d >> 7) << 7];

    float m = fmaxf(maxabs, 1e-30f);
    int ex;
    frexpf(m, &ex);
    float scale = ldexpf(1.0f, ex - 3);
    float qv = rintf(val / scale);
    qv = fminf(7.f, fmaxf(-7.f, qv)) * scale;
    if (!(maxabs > 0.f)) qv = 0.f;

    kq[(size_t)r * HD_ + d] = __float2bfloat16(qv);
}

// ------- V: fp32 [B,NKV,S,HD] -> bf16 limbs, transposed d-major [B,NKV,HD,S] -------
__global__ __launch_bounds__(256)
void v_split_t(const float* __restrict__ v,
               __nv_bfloat16* __restrict__ vh, __nv_bfloat16* __restrict__ vl)
{
    __shared__ float sm[64][65];
    const int s0 = blockIdx.x * 64, d0 = blockIdx.y * 64, bk = blockIdx.z;
    const int tid = threadIdx.x, lane = tid & 31, wid = tid >> 5;
    const float* base = v + ((size_t)bk * S_ + s0) * HD_ + d0;
    for (int i = tid; i < 64*16; i += 256) {
        int r = i >> 4, c = (i & 15) * 4;
        float4 t = *(const float4*)&base[(size_t)r * HD_ + c];
        sm[r][c] = t.x; sm[r][c+1] = t.y; sm[r][c+2] = t.z; sm[r][c+3] = t.w;
    }
    __syncthreads();
    for (int dr = wid; dr < 64; dr += 8) {
        float a  = sm[lane*2][dr];
        float b2 = sm[lane*2+1][dr];
        __nv_bfloat16 h0 = __float2bfloat16(a);
        __nv_bfloat16 h1 = __float2bfloat16(b2);
        uint32_t ph = packbf(h0, h1);
        uint32_t pl = packbf(__float2bfloat16(a  - __bfloat162float(h0)),
                             __float2bfloat16(b2 - __bfloat162float(h1)));
        size_t off = ((size_t)bk * HD_ + d0 + dr) * S_ + s0 + lane*2;
        *(uint32_t*)&vh[off] = ph;
        *(uint32_t*)&vl[off] = pl;
    }
}

// ---------------- tensor-core flash attention (causal, GQA) ----------------
__global__ __launch_bounds__(256)
void attn_mma(const __nv_bfloat16* __restrict__ qh, const __nv_bfloat16* __restrict__ ql,
              const __nv_bfloat16* __restrict__ kq,
              const __nv_bfloat16* __restrict__ vh, const __nv_bfloat16* __restrict__ vl,
              float* __restrict__ o)
{
    extern __shared__ __nv_bfloat16 smb[];
    __nv_bfloat16 (*Qhs)[264] = (__nv_bfloat16(*)[264])(smb);
    __nv_bfloat16 (*Qls)[264] = (__nv_bfloat16(*)[264])(smb + 64*264);
    __nv_bfloat16 (*Ks )[264] = (__nv_bfloat16(*)[264])(smb + 2*64*264);
    __nv_bfloat16 (*Vhs)[72]  = (__nv_bfloat16(*)[72]) (smb + 3*64*264);
    __nv_bfloat16 (*Vls)[72]  = (__nv_bfloat16(*)[72]) (smb + 3*64*264 + 256*72);
    __nv_bfloat16 (*Phs)[72]  = (__nv_bfloat16(*)[72]) (smb + 3*64*264 + 2*256*72);
    __nv_bfloat16 (*Pls)[72]  = (__nv_bfloat16(*)[72]) (smb + 3*64*264 + 2*256*72 + 64*72);
    float* scorr = (float*)(smb + 3*64*264 + 2*256*72 + 2*64*72);

    const int iq = blockIdx.x, h = blockIdx.y, b = blockIdx.z;
    const int kvb = b * NKV_ + (h >> 1);          // NREP_ = 2
    const int tid = threadIdx.x, lane = tid & 31, wid = tid >> 5;

    const size_t qrow0 = ((size_t)(b*NH_ + h) * S_ + (size_t)iq * 64);
    for (int i = tid; i < 64*32; i += 256) {
        int r = i >> 5, c = (i & 31) * 8;
        *(uint4*)&Qhs[r][c] = *(const uint4*)&qh[(qrow0 + r) * HD_ + c];
        *(uint4*)&Qls[r][c] = *(const uint4*)&ql[(qrow0 + r) * HD_ + c];
    }

    float oc[16][4];
#pragma unroll
    for (int t = 0; t < 16; t++)
#pragma unroll
        for (int e = 0; e < 4; e++) oc[t][e] = 0.f;
    float mrun[2] = {-1e30f, -1e30f};
    float lrun[2] = {0.f, 0.f};

    for (int j = 0; j <= iq; j++) {
        const int k0 = j * 64;
        __syncthreads();
        for (int i = tid; i < 64*32; i += 256) {
            int r = i >> 5, c = (i & 31) * 8;
            *(uint4*)&Ks[r][c] = *(const uint4*)&kq[((size_t)kvb * S_ + k0 + r) * HD_ + c];
        }
        for (int i = tid; i < 256*8; i += 256) {
            int r = i >> 3, c = (i & 7) * 8;
            *(uint4*)&Vhs[r][c] = *(const uint4*)&vh[((size_t)kvb * HD_ + r) * S_ + k0 + c];
            *(uint4*)&Vls[r][c] = *(const uint4*)&vl[((size_t)kvb * HD_ + r) * S_ + k0 + c];
        }
        __syncthreads();

        if (wid < 4) {
            const int qb = wid * 16;
            float sc[8][4];
#pragma unroll
            for (int t = 0; t < 8; t++)
#pragma unroll
                for (int e = 0; e < 4; e++) sc[t][e] = 0.f;

            for (int ks = 0; ks < 256; ks += 16) {
                uint32_t Ah[4], Al[4];
                const int ar = qb + (lane & 15);
                const int ak = ks + ((lane >> 4) << 3);
                LDSM4(Ah, s2u(&Qhs[ar][ak]));
                LDSM4(Al, s2u(&Qls[ar][ak]));
                uint32_t Bk[4][4];
#pragma unroll
                for (int g = 0; g < 4; g++) {
                    const int br = g*16 + (lane & 7) + ((lane >> 4) << 3);
                    const int bk = ks + (((lane >> 3) & 1) << 3);
                    LDSM4(Bk[g], s2u(&Ks[br][bk]));
                }
#pragma unroll
                for (int t = 0; t < 8; t++) {
                    const int g = t >> 1, p = (t & 1) << 1;
                    MMA_BF16(sc[t], Ah, Bk[g][p], Bk[g][p+1]);
                    MMA_BF16(sc[t], Al, Bk[g][p], Bk[g][p+1]);
                }
            }

            const bool diag = (j == iq);
            const int r0 = lane >> 2;
#pragma unroll
            for (int rr = 0; rr < 2; rr++) {
                const int rloc = qb + r0 + rr*8;
                const int rg = iq*64 + rloc;
                float mx = -1e30f;
#pragma unroll
                for (int t = 0; t < 8; t++) {
#pragma unroll
                    for (int e = 0; e < 2; e++) {
                        float sv = sc[t][rr*2 + e] * 0.0625f;
                        const int cg = k0 + t*8 + (lane & 3)*2 + e;
                        if (diag && cg > rg) sv = -1e30f;
                        sc[t][rr*2 + e] = sv;
                        mx = fmaxf(mx, sv);
                    }
                }
                mx = fmaxf(mx, __shfl_xor_sync(0xffffffffu, mx, 1));
                mx = fmaxf(mx, __shfl_xor_sync(0xffffffffu, mx, 2));
                const float mnew = fmaxf(mrun[rr], mx);
                const float corr = __expf(mrun[rr] - mnew);
                mrun[rr] = mnew;
                float ls = 0.f;
#pragma unroll
                for (int t = 0; t < 8; t++) {
                    float p0 = __expf(sc[t][rr*2 + 0] - mnew);
                    float p1 = __expf(sc[t][rr*2 + 1] - mnew);
                    ls += p0 + p1;
                    __nv_bfloat16 h0 = __float2bfloat16(p0);
                    __nv_bfloat16 h1 = __float2bfloat16(p1);
                    const int col = t*8 + (lane & 3)*2;
                    *(uint32_t*)&Phs[rloc][col] = packbf(h0, h1);
                    *(uint32_t*)&Pls[rloc][col] =
                        packbf(__float2bfloat16(p0 - __bfloat162float(h0)),
                               __float2bfloat16(p1 - __bfloat162float(h1)));
                }
                ls += __shfl_xor_sync(0xffffffffu, ls, 1);
                ls += __shfl_xor_sync(0xffffffffu, ls, 2);
                lrun[rr] = lrun[rr] * corr + ls;
                if ((lane & 3) == 0) scorr[rloc] = corr;
            }
        }
        __syncthreads();

        {
            const int qb = (wid & 3) * 16, db = (wid >> 2) * 128;
            const float c0 = scorr[qb + (lane >> 2)];
            const float c1 = scorr[qb + (lane >> 2) + 8];
#pragma unroll
            for (int t = 0; t < 16; t++) {
                oc[t][0] *= c0; oc[t][1] *= c0;
                oc[t][2] *= c1; oc[t][3] *= c1;
            }
#pragma unroll
            for (int kk = 0; kk < 64; kk += 16) {
                uint32_t Aph[4], Apl[4];
                const int ar = qb + (lane & 15);
                const int ak = kk + ((lane >> 4) << 3);
                LDSM4(Aph, s2u(&Phs[ar][ak]));
                LDSM4(Apl, s2u(&Pls[ar][ak]));
#pragma unroll
                for (int g = 0; g < 8; g++) {
                    uint32_t Bvh[4], Bvl[4];
                    const int vr = db + g*16 + (lane & 7) + ((lane >> 4) << 3);
                    const int vc = kk + (((lane >> 3) & 1) << 3);
                    LDSM4(Bvh, s2u(&Vhs[vr][vc]));
                    LDSM4(Bvl, s2u(&Vls[vr][vc]));
#pragma unroll
                    for (int tt = 0; tt < 2; tt++) {
                        const int t = g*2 + tt, p = tt << 1;
                        MMA_BF16(oc[t], Aph, Bvh[p], Bvh[p+1]);
                        MMA_BF16(oc[t], Apl, Bvh[p], Bvh[p+1]);
                        MMA_BF16(oc[t], Aph, Bvl[p], Bvl[p+1]);
                    }
                }
            }
        }
    }

    __syncthreads();
    if (wid < 4 && (lane & 3) == 0) {
        scorr[wid*16 + (lane >> 2)]     = 1.f / lrun[0];
        scorr[wid*16 + (lane >> 2) + 8] = 1.f / lrun[1];
    }
    __syncthreads();

    {
        const int qb = (wid & 3) * 16, db = (wid >> 2) * 128;
        const float i0 = scorr[qb + (lane >> 2)];
        const float i1 = scorr[qb + (lane >> 2) + 8];
        const int r0g = iq*64 + qb + (lane >> 2);
#pragma unroll
        for (int t = 0; t < 16; t++) {
            const int col = db + t*8 + (lane & 3)*2;
            float* p0 = o + ((size_t)b*S_ + r0g    ) * (NH_*HD_) + (size_t)h*HD_ + col;
            float* p1 = o + ((size_t)b*S_ + r0g + 8) * (NH_*HD_) + (size_t)h*HD_ + col;
            *(float2*)p0 = make_float2(oc[t][0]*i0, oc[t][1]*i0);
            *(float2*)p1 = make_float2(oc[t][2]*i1, oc[t][3]*i1);
        }
    }
}

// ---------------- launcher ----------------
extern "C" void kernel_launch(void* const* d_in, const int* in_sizes, int n_in,
                              void* d_out, int out_size)
{
    const float* hidden = (const float*)d_in[0];
    const float* Wq     = (const float*)d_in[1];
    const float* Wk     = (const float*)d_in[2];
    const float* Wv     = (const float*)d_in[3];
    const float* Wo     = (const float*)d_in[4];
    const float* cosp   = (const float*)d_in[5];
    const float* sinp   = (const float*)d_in[6];
    float* out = (float*)d_out;
    (void)in_sizes; (void)n_in; (void)out_size;

    float *q, *k, *vv, *oo;
    __nv_bfloat16 *qhp, *qlp, *kqp, *vhp, *vlp;
    cudaGetSymbolAddress((void**)&q,   g_q);
    cudaGetSymbolAddress((void**)&k,   g_k);
    cudaGetSymbolAddress((void**)&vv,  g_v);
    cudaGetSymbolAddress((void**)&oo,  g_o);
    cudaGetSymbolAddress((void**)&qhp, g_qh);
    cudaGetSymbolAddress((void**)&qlp, g_ql);
    cudaGetSymbolAddress((void**)&kqp, g_kq);
    cudaGetSymbolAddress((void**)&vhp, g_vh);
    cudaGetSymbolAddress((void**)&vlp, g_vl);

    const int M = B_ * S_;  // 4096
    dim3 blk(256);

    const int smemG = 2 * 4 * 128 * 40 * (int)sizeof(__nv_bfloat16);  // 81920
    cudaFuncSetAttribute(proj_fused,   cudaFuncAttributeMaxDynamicSharedMemorySize, smemG);
    cudaFuncSetAttribute(gemm_mma2<0>, cudaFuncAttributeMaxDynamicSharedMemorySize, smemG);

    // fused Q (tensor) + K (fp32 FFMA, bit-identical path) + V (tensor) projections
    proj_fused<<<2048, blk, smemG>>>(hidden, Wq, Wk, Wv, q, k, vv);

    rope_q_split<<<(B_*NH_*S_*128)/256, 256>>>(q, qhp, qlp, cosp, sinp);
    rope_quant_k<<<B_*NKV_*S_, 256>>>(k, kqp, cosp, sinp);
    v_split_t<<<dim3(S_/64, HD_/64, B_*NKV_), 256>>>(vv, vhp, vlp);

    const int smemA = (3*64*264 + 2*256*72 + 2*64*72) * (int)sizeof(__nv_bfloat16) + 64*(int)sizeof(float);
    cudaFuncSetAttribute(attn_mma, cudaFuncAttributeMaxDynamicSharedMemorySize, smemA);
    attn_mma<<<dim3(S_/64, NH_, B_), 256, smemA>>>(qhp, qlp, kqp, vhp, vlp, oo);

    // output projection: tensor 2-limb
    gemm_mma2<0><<<dim3(HID_/128, M/128), blk, smemG>>>(oo, Wo, out, M, HID_, NH_*HD_, 0);
}

// round 11
// speedup vs baseline: 1.1788x; 1.1788x over previous
#include <cuda_runtime.h>
#include <cuda_bf16.h>
#include <cstdint>
#include <math.h>

#define B_   2
#define S_   2048
#define HID_ 3072
#define NH_  16
#define NKV_ 8
#define HD_  256
#define NREP_ 2

// ---------------- scratch (device globals; no allocation allowed) ----------------
__device__ float g_q [(size_t)B_*NH_ *S_*HD_];   // [B,NH,S,HD] fp32 (pre-rope)
__device__ float g_k [(size_t)B_*NKV_*S_*HD_];   // [B,NKV,S,HD] fp32 (pre-rope)
__device__ float g_v [(size_t)B_*NKV_*S_*HD_];   // [B,NKV,S,HD] fp32

__device__ __nv_bfloat16 g_qh[(size_t)B_*NH_ *S_*HD_];  // Q hi limb [B,NH,S,HD]
__device__ __nv_bfloat16 g_ql[(size_t)B_*NH_ *S_*HD_];  // Q lo limb
__device__ __nv_bfloat16 g_kq[(size_t)B_*NKV_*S_*HD_];  // quantized K (exact bf16)
__device__ __nv_bfloat16 g_vh[(size_t)B_*NKV_*HD_*S_];  // V hi limb, d-major
__device__ __nv_bfloat16 g_vl[(size_t)B_*NKV_*HD_*S_];  // V lo limb, d-major

// pre-split operands for tensor GEMMs
__device__ __nv_bfloat16 g_hh [(size_t)B_*S_*HID_];     // hidden hi
__device__ __nv_bfloat16 g_hl [(size_t)B_*S_*HID_];     // hidden lo
__device__ __nv_bfloat16 g_wqh[(size_t)NH_*HD_*HID_];
__device__ __nv_bfloat16 g_wql[(size_t)NH_*HD_*HID_];
__device__ __nv_bfloat16 g_wvh[(size_t)NKV_*HD_*HID_];
__device__ __nv_bfloat16 g_wvl[(size_t)NKV_*HD_*HID_];
__device__ __nv_bfloat16 g_woh[(size_t)HID_*NH_*HD_];
__device__ __nv_bfloat16 g_wol[(size_t)HID_*NH_*HD_];
__device__ __nv_bfloat16 g_oh [(size_t)B_*S_*NH_*HD_];  // attention out hi [B,S,NH*HD]
__device__ __nv_bfloat16 g_ol [(size_t)B_*S_*NH_*HD_];  // attention out lo

// ================= helpers =================
__device__ __forceinline__ uint32_t s2u(const void* p) {
    return (uint32_t)__cvta_generic_to_shared(p);
}

#define LDSM4(r, addr)                                                          \
    asm volatile("ldmatrix.sync.aligned.m8n8.x4.shared.b16 {%0,%1,%2,%3}, [%4];"\
                 : "=r"((r)[0]), "=r"((r)[1]), "=r"((r)[2]), "=r"((r)[3])       \
                 : "r"(addr))

#define MMA_BF16(c, a, b0, b1)                                                  \
    asm volatile("mma.sync.aligned.m16n8k16.row.col.f32.bf16.bf16.f32 "         \
                 "{%0,%1,%2,%3}, {%4,%5,%6,%7}, {%8,%9}, {%0,%1,%2,%3};"        \
                 : "+f"((c)[0]), "+f"((c)[1]), "+f"((c)[2]), "+f"((c)[3])       \
                 : "r"((a)[0]), "r"((a)[1]), "r"((a)[2]), "r"((a)[3]),          \
                   "r"(b0), "r"(b1))

__device__ __forceinline__ uint32_t packbf(__nv_bfloat16 a, __nv_bfloat16 b) {
    return (uint32_t)__bfloat16_as_ushort(a) | ((uint32_t)__bfloat16_as_ushort(b) << 16);
}

__device__ __forceinline__ void split2(float x0, float x1, uint32_t* p) {
    __nv_bfloat16 h0 = __float2bfloat16(x0);
    __nv_bfloat16 h1 = __float2bfloat16(x1);
    p[0] = packbf(h0, h1);
    float r0 = x0 - __bfloat162float(h0);
    float r1 = x1 - __bfloat162float(h1);
    p[1] = packbf(__float2bfloat16(r0), __float2bfloat16(r1));
}

// ======== prep: split fp32 arrays -> bf16 hi/lo (identical split2 math) ========
__global__ __launch_bounds__(256)
void split_all(const float* __restrict__ hidden, const float* __restrict__ Wq,
               const float* __restrict__ Wv,     const float* __restrict__ Wo,
               __nv_bfloat16* __restrict__ hh,  __nv_bfloat16* __restrict__ hl,
               __nv_bfloat16* __restrict__ wqh, __nv_bfloat16* __restrict__ wql,
               __nv_bfloat16* __restrict__ wvh, __nv_bfloat16* __restrict__ wvl,
               __nv_bfloat16* __restrict__ woh, __nv_bfloat16* __restrict__ wol)
{
    const size_t i4 = (size_t)blockIdx.x * 256 + threadIdx.x;  // float4 index
    const int which = blockIdx.y;
    const float* src; __nv_bfloat16 *dh, *dl; size_t n4;
    if (which == 0)      { src = hidden; dh = hh;  dl = hl;  n4 = (size_t)B_*S_*HID_/4; }
    else if (which == 1) { src = Wq;     dh = wqh; dl = wql; n4 = (size_t)NH_*HD_*HID_/4; }
    else if (which == 2) { src = Wv;     dh = wvh; dl = wvl; n4 = (size_t)NKV_*HD_*HID_/4; }
    else                 { src = Wo;     dh = woh; dl = wol; n4 = (size_t)HID_*NH_*HD_/4; }
    if (i4 >= n4) return;
    float4 v = ((const float4*)src)[i4];
    uint32_t p0[2], p1[2];
    split2(v.x, v.y, p0);
    split2(v.z, v.w, p1);
    ((uint2*)dh)[i4] = make_uint2(p0[0], p1[0]);
    ((uint2*)dl)[i4] = make_uint2(p0[1], p1[1]);
}

// ================= fp32 NT SGEMM (K projection — DO NOT ALTER OPS) ======
template<int MODE>
__global__ __launch_bounds__(256)
void gemm_nt(const float* __restrict__ A, const float* __restrict__ W,
             float* __restrict__ C, int M, int N, int K, int H)
{
    __shared__ float As[16][132];
    __shared__ float Bs[16][132];
    const int tid = threadIdx.x;
    const int tx = tid & 15, ty = tid >> 4;
    const int m0 = blockIdx.y * 128, n0 = blockIdx.x * 128;
    const int lr = tid >> 2;
    const int lk = (tid & 3) << 2;

    const float* Ap  = A + (size_t)(m0 + lr) * K + lk;
    const float* Ap2 = Ap + (size_t)64 * K;
    const float* Wp  = W + (size_t)(n0 + lr) * K + lk;
    const float* Wp2 = Wp + (size_t)64 * K;

    float acc[8][8];
#pragma unroll
    for (int i = 0; i < 8; i++)
#pragma unroll
        for (int j = 0; j < 8; j++) acc[i][j] = 0.f;

    for (int k0 = 0; k0 < K; k0 += 16) {
        float4 a0 = *(const float4*)(Ap  + k0);
        float4 a1 = *(const float4*)(Ap2 + k0);
        float4 w0 = *(const float4*)(Wp  + k0);
        float4 w1 = *(const float4*)(Wp2 + k0);
        __syncthreads();
        As[lk+0][lr]    = a0.x; As[lk+1][lr]    = a0.y; As[lk+2][lr]    = a0.z; As[lk+3][lr]    = a0.w;
        As[lk+0][lr+64] = a1.x; As[lk+1][lr+64] = a1.y; As[lk+2][lr+64] = a1.z; As[lk+3][lr+64] = a1.w;
        Bs[lk+0][lr]    = w0.x; Bs[lk+1][lr]    = w0.y; Bs[lk+2][lr]    = w0.z; Bs[lk+3][lr]    = w0.w;
        Bs[lk+0][lr+64] = w1.x; Bs[lk+1][lr+64] = w1.y; Bs[lk+2][lr+64] = w1.z; Bs[lk+3][lr+64] = w1.w;
        __syncthreads();
#pragma unroll
        for (int kk = 0; kk < 16; kk++) {
            float4 fa0 = *(const float4*)&As[kk][ty*4];
            float4 fa1 = *(const float4*)&As[kk][ty*4+64];
            float4 fb0 = *(const float4*)&Bs[kk][tx*4];
            float4 fb1 = *(const float4*)&Bs[kk][tx*4+64];
            float av[8] = {fa0.x,fa0.y,fa0.z,fa0.w, fa1.x,fa1.y,fa1.z,fa1.w};
            float bv[8] = {fb0.x,fb0.y,fb0.z,fb0.w, fb1.x,fb1.y,fb1.z,fb1.w};
#pragma unroll
            for (int i = 0; i < 8; i++)
#pragma unroll
                for (int j = 0; j < 8; j++) acc[i][j] += av[i]*bv[j];
        }
    }

#pragma unroll
    for (int i = 0; i < 8; i++) {
        int row = m0 + ty*4 + (i & 3) + (i >> 2) * 64;
#pragma unroll
        for (int jh = 0; jh < 2; jh++) {
            int col = n0 + tx*4 + jh*64;
            float4 vout = make_float4(acc[i][jh*4+0], acc[i][jh*4+1],
                                      acc[i][jh*4+2], acc[i][jh*4+3]);
            if (MODE == 0) {
                *(float4*)(C + (size_t)row * N + col) = vout;
            } else {
                int b = row >> 11, s = row & (S_-1);
                int h = col >> 8,  hd = col & (HD_-1);
                *(float4*)(C + (((size_t)(b*H + h) * S_ + s) * HD_ + hd)) = vout;
            }
        }
    }
}

// ======== 2-limb bf16 tensor GEMM on PRE-SPLIT operands, double-buffered ========
// C = A[M,K] * W[N,K]^T with A = Ah+Al, W = Bh+Bl; products hh, lh, hl.
// MODE 0: C row-major. MODE 1: head-split.
template<int MODE>
__global__ __launch_bounds__(256)
void gemm_pre(const __nv_bfloat16* __restrict__ Ah, const __nv_bfloat16* __restrict__ Al,
              const __nv_bfloat16* __restrict__ Bh, const __nv_bfloat16* __restrict__ Bl,
              float* __restrict__ C, int M, int N, int K, int H)
{
    extern __shared__ __nv_bfloat16 dsm[];
    auto tile = [&](int t) -> __nv_bfloat16 (*)[40] {
        return reinterpret_cast<__nv_bfloat16 (*)[40]>(dsm + (size_t)t * 128 * 40);
    };

    const int tid  = threadIdx.x;
    const int lane = tid & 31, wid = tid >> 5;
    const int wm = wid >> 2;
    const int wn = wid & 3;
    const int m0 = blockIdx.y * 128, n0 = blockIdx.x * 128;

    const int lr = tid >> 1;
    const int lc = (tid & 1) << 4;

    const __nv_bfloat16* pAh = Ah + (size_t)(m0 + lr) * K + lc;
    const __nv_bfloat16* pAl = Al + (size_t)(m0 + lr) * K + lc;
    const __nv_bfloat16* pBh = Bh + (size_t)(n0 + lr) * K + lc;
    const __nv_bfloat16* pBl = Bl + (size_t)(n0 + lr) * K + lc;

    float acc[4][4][4];
#pragma unroll
    for (int mt = 0; mt < 4; mt++)
#pragma unroll
        for (int nt = 0; nt < 4; nt++)
#pragma unroll
            for (int e = 0; e < 4; e++) acc[mt][nt][e] = 0.f;

    uint4 rah0, rah1, ral0, ral1, rbh0, rbh1, rbl0, rbl1;
    auto load_tile = [&](int k0) {
        rah0 = *(const uint4*)(pAh + k0);  rah1 = *(const uint4*)(pAh + k0 + 8);
        ral0 = *(const uint4*)(pAl + k0);  ral1 = *(const uint4*)(pAl + k0 + 8);
        rbh0 = *(const uint4*)(pBh + k0);  rbh1 = *(const uint4*)(pBh + k0 + 8);
        rbl0 = *(const uint4*)(pBl + k0);  rbl1 = *(const uint4*)(pBl + k0 + 8);
    };
    auto store_tile = [&](int buf) {
        *(uint4*)&tile(buf*4 + 0)[lr][lc]     = rah0;
        *(uint4*)&tile(buf*4 + 0)[lr][lc + 8] = rah1;
        *(uint4*)&tile(buf*4 + 1)[lr][lc]     = ral0;
        *(uint4*)&tile(buf*4 + 1)[lr][lc + 8] = ral1;
        *(uint4*)&tile(buf*4 + 2)[lr][lc]     = rbh0;
        *(uint4*)&tile(buf*4 + 2)[lr][lc + 8] = rbh1;
        *(uint4*)&tile(buf*4 + 3)[lr][lc]     = rbl0;
        *(uint4*)&tile(buf*4 + 3)[lr][lc + 8] = rbl1;
    };

    load_tile(0);
    store_tile(0);
    __syncthreads();
    int cur = 0;

    for (int k0 = 0; k0 < K; k0 += 32) {
        const bool more = (k0 + 32 < K);
        if (more) load_tile(k0 + 32);

#pragma unroll
        for (int ks = 0; ks < 32; ks += 16) {
            uint32_t Bf[2][2][4];
#pragma unroll
            for (int l = 0; l < 2; l++) {
#pragma unroll
                for (int g = 0; g < 2; g++) {
                    const int br = wn * 32 + g * 16 + (lane & 7) + ((lane >> 4) << 3);
                    const int bk = ks + (((lane >> 3) & 1) << 3);
                    LDSM4(Bf[l][g], s2u(&tile(cur*4 + 2 + l)[br][bk]));
                }
            }
#pragma unroll
            for (int mt = 0; mt < 4; mt++) {
                uint32_t Af[2][4];
                const int ar = wm * 64 + mt * 16 + (lane & 15);
                const int ak = ks + ((lane >> 4) << 3);
                LDSM4(Af[0], s2u(&tile(cur*4 + 0)[ar][ak]));
                LDSM4(Af[1], s2u(&tile(cur*4 + 1)[ar][ak]));
#pragma unroll
                for (int nt = 0; nt < 4; nt++) {
                    const int g = nt >> 1, p = (nt & 1) << 1;
                    float* c = acc[mt][nt];
                    MMA_BF16(c, Af[0], Bf[0][g][p], Bf[0][g][p+1]);   // hh
                    MMA_BF16(c, Af[1], Bf[0][g][p], Bf[0][g][p+1]);   // lh
                    MMA_BF16(c, Af[0], Bf[1][g][p], Bf[1][g][p+1]);   // hl
                }
            }
        }

        if (more) store_tile(cur ^ 1);
        __syncthreads();
        cur ^= 1;
    }

#pragma unroll
    for (int mt = 0; mt < 4; mt++) {
        const int row0 = m0 + wm * 64 + mt * 16 + (lane >> 2);
#pragma unroll
        for (int nt = 0; nt < 4; nt++) {
            const int col = n0 + wn * 32 + nt * 8 + ((lane & 3) << 1);
            float2 v0 = make_float2(acc[mt][nt][0], acc[mt][nt][1]);
            float2 v1 = make_float2(acc[mt][nt][2], acc[mt][nt][3]);
            if (MODE == 0) {
                *(float2*)(C + (size_t)row0       * N + col) = v0;
                *(float2*)(C + (size_t)(row0 + 8) * N + col) = v1;
            } else {
                const int h = col >> 8, hd = col & (HD_ - 1);
#pragma unroll
                for (int rr = 0; rr < 2; rr++) {
                    const int row = row0 + rr * 8;
                    const int b = row >> 11, s = row & (S_ - 1);
                    *(float2*)(C + (((size_t)(b * H + h) * S_ + s) * HD_ + hd)) =
                        rr ? v1 : v0;
                }
            }
        }
    }
}

// ---------------- RoPE on Q -> bf16 limbs ----------------
__global__ void rope_q_split(const float* __restrict__ q,
                             __nv_bfloat16* __restrict__ qh,
                             __nv_bfloat16* __restrict__ ql,
                             const float* __restrict__ cosp,
                             const float* __restrict__ sinp)
{
    size_t idx = (size_t)blockIdx.x * blockDim.x + threadIdx.x; // B*NH*S*128
    int d = (int)(idx & 127);
    size_t rrow = idx >> 7;
    int s = (int)(rrow & (S_-1));
    const float* row = q + rrow * HD_;
    float x1 = row[d], x2 = row[d + 128];
    float c1 = cosp[s*HD_ + d],       s1 = sinp[s*HD_ + d];
    float c2 = cosp[s*HD_ + d + 128], s2 = sinp[s*HD_ + d + 128];
    float v1 = x1 * c1 - x2 * s1;
    float v2 = x2 * c2 + x1 * s2;
    __nv_bfloat16 h1 = __float2bfloat16(v1);
    __nv_bfloat16 h2 = __float2bfloat16(v2);
    qh[rrow*HD_ + d]       = h1;
    qh[rrow*HD_ + d + 128] = h2;
    ql[rrow*HD_ + d]       = __float2bfloat16(v1 - __bfloat162float(h1));
    ql[rrow*HD_ + d + 128] = __float2bfloat16(v2 - __bfloat162float(h2));
}

// ------- RoPE + BFP quantize K -> exact bf16, s-major [B,NKV,S,HD] -------
__global__ __launch_bounds__(256)
void rope_quant_k(const float* __restrict__ k, __nv_bfloat16* __restrict__ kq,
                  const float* __restrict__ cosp, const float* __restrict__ sinp)
{
    int r = blockIdx.x;                 // (b*NKV+kv)*S + s
    int s = r & (S_-1);
    int d = threadIdx.x;
    const float* row = k + (size_t)r * HD_;
    float x = row[d];
    float other = (d < 128) ? -row[d + 128] : row[d - 128];
    float val = x * cosp[s*HD_ + d] + other * sinp[s*HD_ + d];

    __shared__ float red[256];
    red[d] = fabsf(val);
    __syncthreads();
    for (int off = 64; off > 0; off >>= 1) {
        if ((d & 127) < off) red[d] = fmaxf(red[d], red[d + off]);
        __syncthreads();
    }
    float maxabs = red[(d >> 7) << 7];

    float m = fmaxf(maxabs, 1e-30f);
    int ex;
    frexpf(m, &ex);
    float scale = ldexpf(1.0f, ex - 3);
    float qv = rintf(val / scale);
    qv = fminf(7.f, fmaxf(-7.f, qv)) * scale;
    if (!(maxabs > 0.f)) qv = 0.f;

    kq[(size_t)r * HD_ + d] = __float2bfloat16(qv);
}

// ------- V: fp32 [B,NKV,S,HD] -> bf16 limbs, transposed d-major [B,NKV,HD,S] -------
__global__ __launch_bounds__(256)
void v_split_t(const float* __restrict__ v,
               __nv_bfloat16* __restrict__ vh, __nv_bfloat16* __restrict__ vl)
{
    __shared__ float sm[64][65];
    const int s0 = blockIdx.x * 64, d0 = blockIdx.y * 64, bk = blockIdx.z;
    const int tid = threadIdx.x, lane = tid & 31, wid = tid >> 5;
    const float* base = v + ((size_t)bk * S_ + s0) * HD_ + d0;
    for (int i = tid; i < 64*16; i += 256) {
        int r = i >> 4, c = (i & 15) * 4;
        float4 t = *(const float4*)&base[(size_t)r * HD_ + c];
        sm[r][c] = t.x; sm[r][c+1] = t.y; sm[r][c+2] = t.z; sm[r][c+3] = t.w;
    }
    __syncthreads();
    for (int dr = wid; dr < 64; dr += 8) {
        float a  = sm[lane*2][dr];
        float b2 = sm[lane*2+1][dr];
        __nv_bfloat16 h0 = __float2bfloat16(a);
        __nv_bfloat16 h1 = __float2bfloat16(b2);
        uint32_t ph = packbf(h0, h1);
        uint32_t pl = packbf(__float2bfloat16(a  - __bfloat162float(h0)),
                             __float2bfloat16(b2 - __bfloat162float(h1)));
        size_t off = ((size_t)bk * HD_ + d0 + dr) * S_ + s0 + lane*2;
        *(uint32_t*)&vh[off] = ph;
        *(uint32_t*)&vl[off] = pl;
    }
}

// ---------------- tensor-core flash attention (causal, GQA) ----------------
// outputs O as bf16 limbs (hi/lo) directly -> feeds gemm_pre<0> without a prep pass.
__global__ __launch_bounds__(256)
void attn_mma(const __nv_bfloat16* __restrict__ qh, const __nv_bfloat16* __restrict__ ql,
              const __nv_bfloat16* __restrict__ kq,
              const __nv_bfloat16* __restrict__ vh, const __nv_bfloat16* __restrict__ vl,
              __nv_bfloat16* __restrict__ oh, __nv_bfloat16* __restrict__ ol)
{
    extern __shared__ __nv_bfloat16 smb[];
    __nv_bfloat16 (*Qhs)[264] = (__nv_bfloat16(*)[264])(smb);
    __nv_bfloat16 (*Qls)[264] = (__nv_bfloat16(*)[264])(smb + 64*264);
    __nv_bfloat16 (*Ks )[264] = (__nv_bfloat16(*)[264])(smb + 2*64*264);
    __nv_bfloat16 (*Vhs)[72]  = (__nv_bfloat16(*)[72]) (smb + 3*64*264);
    __nv_bfloat16 (*Vls)[72]  = (__nv_bfloat16(*)[72]) (smb + 3*64*264 + 256*72);
    __nv_bfloat16 (*Phs)[72]  = (__nv_bfloat16(*)[72]) (smb + 3*64*264 + 2*256*72);
    __nv_bfloat16 (*Pls)[72]  = (__nv_bfloat16(*)[72]) (smb + 3*64*264 + 2*256*72 + 64*72);
    float* scorr = (float*)(smb + 3*64*264 + 2*256*72 + 2*64*72);

    const int iq = blockIdx.x, h = blockIdx.y, b = blockIdx.z;
    const int kvb = b * NKV_ + (h >> 1);          // NREP_ = 2
    const int tid = threadIdx.x, lane = tid & 31, wid = tid >> 5;

    const size_t qrow0 = ((size_t)(b*NH_ + h) * S_ + (size_t)iq * 64);
    for (int i = tid; i < 64*32; i += 256) {
        int r = i >> 5, c = (i & 31) * 8;
        *(uint4*)&Qhs[r][c] = *(const uint4*)&qh[(qrow0 + r) * HD_ + c];
        *(uint4*)&Qls[r][c] = *(const uint4*)&ql[(qrow0 + r) * HD_ + c];
    }

    float oc[16][4];
#pragma unroll
    for (int t = 0; t < 16; t++)
#pragma unroll
        for (int e = 0; e < 4; e++) oc[t][e] = 0.f;
    float mrun[2] = {-1e30f, -1e30f};
    float lrun[2] = {0.f, 0.f};

    for (int j = 0; j <= iq; j++) {
        const int k0 = j * 64;
        __syncthreads();
        for (int i = tid; i < 64*32; i += 256) {
            int r = i >> 5, c = (i & 31) * 8;
            *(uint4*)&Ks[r][c] = *(const uint4*)&kq[((size_t)kvb * S_ + k0 + r) * HD_ + c];
        }
        for (int i = tid; i < 256*8; i += 256) {
            int r = i >> 3, c = (i & 7) * 8;
            *(uint4*)&Vhs[r][c] = *(const uint4*)&vh[((size_t)kvb * HD_ + r) * S_ + k0 + c];
            *(uint4*)&Vls[r][c] = *(const uint4*)&vl[((size_t)kvb * HD_ + r) * S_ + k0 + c];
        }
        __syncthreads();

        if (wid < 4) {
            const int qb = wid * 16;
            float sc[8][4];
#pragma unroll
            for (int t = 0; t < 8; t++)
#pragma unroll
                for (int e = 0; e < 4; e++) sc[t][e] = 0.f;

            for (int ks = 0; ks < 256; ks += 16) {
                uint32_t Ah[4], Al[4];
                const int ar = qb + (lane & 15);
                const int ak = ks + ((lane >> 4) << 3);
                LDSM4(Ah, s2u(&Qhs[ar][ak]));
                LDSM4(Al, s2u(&Qls[ar][ak]));
                uint32_t Bk[4][4];
#pragma unroll
                for (int g = 0; g < 4; g++) {
                    const int br = g*16 + (lane & 7) + ((lane >> 4) << 3);
                    const int bk = ks + (((lane >> 3) & 1) << 3);
                    LDSM4(Bk[g], s2u(&Ks[br][bk]));
                }
#pragma unroll
                for (int t = 0; t < 8; t++) {
                    const int g = t >> 1, p = (t & 1) << 1;
                    MMA_BF16(sc[t], Ah, Bk[g][p], Bk[g][p+1]);
                    MMA_BF16(sc[t], Al, Bk[g][p], Bk[g][p+1]);
                }
            }

            const bool diag = (j == iq);
            const int r0 = lane >> 2;
#pragma unroll
            for (int rr = 0; rr < 2; rr++) {
                const int rloc = qb + r0 + rr*8;
                const int rg = iq*64 + rloc;
                float mx = -1e30f;
#pragma unroll
                for (int t = 0; t < 8; t++) {
#pragma unroll
                    for (int e = 0; e < 2; e++) {
                        float sv = sc[t][rr*2 + e] * 0.0625f;
                        const int cg = k0 + t*8 + (lane & 3)*2 + e;
                        if (diag && cg > rg) sv = -1e30f;
                        sc[t][rr*2 + e] = sv;
                        mx = fmaxf(mx, sv);
                    }
                }
                mx = fmaxf(mx, __shfl_xor_sync(0xffffffffu, mx, 1));
                mx = fmaxf(mx, __shfl_xor_sync(0xffffffffu, mx, 2));
                const float mnew = fmaxf(mrun[rr], mx);
                const float corr = __expf(mrun[rr] - mnew);
                mrun[rr] = mnew;
                float ls = 0.f;
#pragma unroll
                for (int t = 0; t < 8; t++) {
                    float p0 = __expf(sc[t][rr*2 + 0] - mnew);
                    float p1 = __expf(sc[t][rr*2 + 1] - mnew);
                    ls += p0 + p1;
                    __nv_bfloat16 h0 = __float2bfloat16(p0);
                    __nv_bfloat16 h1 = __float2bfloat16(p1);
                    const int col = t*8 + (lane & 3)*2;
                    *(uint32_t*)&Phs[rloc][col] = packbf(h0, h1);
                    *(uint32_t*)&Pls[rloc][col] =
                        packbf(__float2bfloat16(p0 - __bfloat162float(h0)),
                               __float2bfloat16(p1 - __bfloat162float(h1)));
                }
                ls += __shfl_xor_sync(0xffffffffu, ls, 1);
                ls += __shfl_xor_sync(0xffffffffu, ls, 2);
                lrun[rr] = lrun[rr] * corr + ls;
                if ((lane & 3) == 0) scorr[rloc] = corr;
            }
        }
        __syncthreads();

        {
            const int qb = (wid & 3) * 16, db = (wid >> 2) * 128;
            const float c0 = scorr[qb + (lane >> 2)];
            const float c1 = scorr[qb + (lane >> 2) + 8];
#pragma unroll
            for (int t = 0; t < 16; t++) {
                oc[t][0] *= c0; oc[t][1] *= c0;
                oc[t][2] *= c1; oc[t][3] *= c1;
            }
#pragma unroll
            for (int kk = 0; kk < 64; kk += 16) {
                uint32_t Aph[4], Apl[4];
                const int ar = qb + (lane & 15);
                const int ak = kk + ((lane >> 4) << 3);
                LDSM4(Aph, s2u(&Phs[ar][ak]));
                LDSM4(Apl, s2u(&Pls[ar][ak]));
#pragma unroll
                for (int g = 0; g < 8; g++) {
                    uint32_t Bvh[4], Bvl[4];
                    const int vr = db + g*16 + (lane & 7) + ((lane >> 4) << 3);
                    const int vc = kk + (((lane >> 3) & 1) << 3);
                    LDSM4(Bvh, s2u(&Vhs[vr][vc]));
                    LDSM4(Bvl, s2u(&Vls[vr][vc]));
#pragma unroll
                    for (int tt = 0; tt < 2; tt++) {
                        const int t = g*2 + tt, p = tt << 1;
                        MMA_BF16(oc[t], Aph, Bvh[p], Bvh[p+1]);
                        MMA_BF16(oc[t], Apl, Bvh[p], Bvh[p+1]);
                        MMA_BF16(oc[t], Aph, Bvl[p], Bvl[p+1]);
                    }
                }
            }
        }
    }

    __syncthreads();
    if (wid < 4 && (lane & 3) == 0) {
        scorr[wid*16 + (lane >> 2)]     = 1.f / lrun[0];
        scorr[wid*16 + (lane >> 2) + 8] = 1.f / lrun[1];
    }
    __syncthreads();

    {
        const int qb = (wid & 3) * 16, db = (wid >> 2) * 128;
        const float i0 = scorr[qb + (lane >> 2)];
        const float i1 = scorr[qb + (lane >> 2) + 8];
        const int r0g = iq*64 + qb + (lane >> 2);
#pragma unroll
        for (int t = 0; t < 16; t++) {
            const int col = db + t*8 + (lane & 3)*2;
            const size_t off0 = ((size_t)b*S_ + r0g    ) * (NH_*HD_) + (size_t)h*HD_ + col;
            const size_t off1 = ((size_t)b*S_ + r0g + 8) * (NH_*HD_) + (size_t)h*HD_ + col;
            uint32_t p0[2], p1[2];
            split2(oc[t][0]*i0, oc[t][1]*i0, p0);
            split2(oc[t][2]*i1, oc[t][3]*i1, p1);
            *(uint32_t*)&oh[off0] = p0[0];
            *(uint32_t*)&ol[off0] = p0[1];
            *(uint32_t*)&oh[off1] = p1[0];
            *(uint32_t*)&ol[off1] = p1[1];
        }
    }
}

// ---------------- launcher ----------------
extern "C" void kernel_launch(void* const* d_in, const int* in_sizes, int n_in,
                              void* d_out, int out_size)
{
    const float* hidden = (const float*)d_in[0];
    const float* Wq     = (const float*)d_in[1];
    const float* Wk     = (const float*)d_in[2];
    const float* Wv     = (const float*)d_in[3];
    const float* Wo     = (const float*)d_in[4];
    const float* cosp   = (const float*)d_in[5];
    const float* sinp   = (const float*)d_in[6];
    float* out = (float*)d_out;
    (void)in_sizes; (void)n_in; (void)out_size;

    float *q, *k, *vv;
    __nv_bfloat16 *qhp, *qlp, *kqp, *vhp, *vlp;
    __nv_bfloat16 *hh, *hl, *wqh, *wql, *wvh, *wvl, *woh, *wol, *ohp, *olp;
    cudaGetSymbolAddress((void**)&q,   g_q);
    cudaGetSymbolAddress((void**)&k,   g_k);
    cudaGetSymbolAddress((void**)&vv,  g_v);
    cudaGetSymbolAddress((void**)&qhp, g_qh);
    cudaGetSymbolAddress((void**)&qlp, g_ql);
    cudaGetSymbolAddress((void**)&kqp, g_kq);
    cudaGetSymbolAddress((void**)&vhp, g_vh);
    cudaGetSymbolAddress((void**)&vlp, g_vl);
    cudaGetSymbolAddress((void**)&hh,  g_hh);
    cudaGetSymbolAddress((void**)&hl,  g_hl);
    cudaGetSymbolAddress((void**)&wqh, g_wqh);
    cudaGetSymbolAddress((void**)&wql, g_wql);
    cudaGetSymbolAddress((void**)&wvh, g_wvh);
    cudaGetSymbolAddress((void**)&wvl, g_wvl);
    cudaGetSymbolAddress((void**)&woh, g_woh);
    cudaGetSymbolAddress((void**)&wol, g_wol);
    cudaGetSymbolAddress((void**)&ohp, g_oh);
    cudaGetSymbolAddress((void**)&olp, g_ol);

    const int M = B_ * S_;  // 4096
    dim3 blk(256);

    const int smemG = 2 * 4 * 128 * 40 * (int)sizeof(__nv_bfloat16);  // 81920
    cudaFuncSetAttribute(gemm_pre<1>, cudaFuncAttributeMaxDynamicSharedMemorySize, smemG);
    cudaFuncSetAttribute(gemm_pre<0>, cudaFuncAttributeMaxDynamicSharedMemorySize, smemG);

    // pre-split hidden / Wq / Wv / Wo into bf16 limbs (identical split2 math)
    split_all<<<dim3(12288, 4), blk>>>(hidden, Wq, Wv, Wo,
                                       hh, hl, wqh, wql, wvh, wvl, woh, wol);

    // Q projection: tensor 2-limb on pre-split operands
    gemm_pre<1><<<dim3((NH_*HD_)/128,  M/128), blk, smemG>>>(hh, hl, wqh, wql, q,  M, NH_*HD_,  HID_, NH_);
    // K projection: fp32 FFMA (byte-identical path into the BFP quantizer)
    gemm_nt<1><<<dim3((NKV_*HD_)/128, M/128), blk>>>(hidden, Wk, k, M, NKV_*HD_, HID_, NKV_);
    // V projection: tensor 2-limb on pre-split operands
    gemm_pre<1><<<dim3((NKV_*HD_)/128, M/128), blk, smemG>>>(hh, hl, wvh, wvl, vv, M, NKV_*HD_, HID_, NKV_);

    rope_q_split<<<(B_*NH_*S_*128)/256, 256>>>(q, qhp, qlp, cosp, sinp);
    rope_quant_k<<<B_*NKV_*S_, 256>>>(k, kqp, cosp, sinp);
    v_split_t<<<dim3(S_/64, HD_/64, B_*NKV_), 256>>>(vv, vhp, vlp);

    const int smemA = (3*64*264 + 2*256*72 + 2*64*72) * (int)sizeof(__nv_bfloat16) + 64*(int)sizeof(float);
    cudaFuncSetAttribute(attn_mma, cudaFuncAttributeMaxDynamicSharedMemorySize, smemA);
    attn_mma<<<dim3(S_/64, NH_, B_), 256, smemA>>>(qhp, qlp, kqp, vhp, vlp, ohp, olp);

    // output projection: tensor 2-limb, A limbs come straight from attention epilogue
    gemm_pre<0><<<dim3(HID_/128, M/128), blk, smemG>>>(ohp, olp, woh, wol, out, M, HID_, NH_*HD_, 0);
}

// round 12
// speedup vs baseline: 1.2128x; 1.0288x over previous
#include <cuda_runtime.h>
#include <cuda_bf16.h>
#include <cstdint>
#include <math.h>

#define B_   2
#define S_   2048
#define HID_ 3072
#define NH_  16
#define NKV_ 8
#define HD_  256
#define NREP_ 2

// ---------------- scratch (device globals; no allocation allowed) ----------------
__device__ float g_q [(size_t)B_*NH_ *S_*HD_];   // [B,NH,S,HD] fp32 (pre-rope)
__device__ float g_k [(size_t)B_*NKV_*S_*HD_];   // [B,NKV,S,HD] fp32 (pre-rope)
__device__ float g_v [(size_t)B_*NKV_*S_*HD_];   // [B,NKV,S,HD] fp32

__device__ __nv_bfloat16 g_qh[(size_t)B_*NH_ *S_*HD_];  // Q hi limb [B,NH,S,HD]
__device__ __nv_bfloat16 g_ql[(size_t)B_*NH_ *S_*HD_];  // Q lo limb
__device__ __nv_bfloat16 g_kq[(size_t)B_*NKV_*S_*HD_];  // quantized K (exact bf16)
__device__ __nv_bfloat16 g_vh[(size_t)B_*NKV_*HD_*S_];  // V hi limb, d-major
__device__ __nv_bfloat16 g_vl[(size_t)B_*NKV_*HD_*S_];  // V lo limb, d-major

// pre-split operands for tensor GEMMs
__device__ __nv_bfloat16 g_hh [(size_t)B_*S_*HID_];     // hidden hi
__device__ __nv_bfloat16 g_hl [(size_t)B_*S_*HID_];     // hidden lo
__device__ __nv_bfloat16 g_wqh[(size_t)NH_*HD_*HID_];
__device__ __nv_bfloat16 g_wql[(size_t)NH_*HD_*HID_];
__device__ __nv_bfloat16 g_wvh[(size_t)NKV_*HD_*HID_];
__device__ __nv_bfloat16 g_wvl[(size_t)NKV_*HD_*HID_];
__device__ __nv_bfloat16 g_woh[(size_t)HID_*NH_*HD_];
__device__ __nv_bfloat16 g_wol[(size_t)HID_*NH_*HD_];
__device__ __nv_bfloat16 g_oh [(size_t)B_*S_*NH_*HD_];  // attention out hi [B,S,NH*HD]
__device__ __nv_bfloat16 g_ol [(size_t)B_*S_*NH_*HD_];  // attention out lo

// ================= helpers =================
__device__ __forceinline__ uint32_t s2u(const void* p) {
    return (uint32_t)__cvta_generic_to_shared(p);
}

#define LDSM4(r, addr)                                                          \
    asm volatile("ldmatrix.sync.aligned.m8n8.x4.shared.b16 {%0,%1,%2,%3}, [%4];"\
                 : "=r"((r)[0]), "=r"((r)[1]), "=r"((r)[2]), "=r"((r)[3])       \
                 : "r"(addr))

#define MMA_BF16(c, a, b0, b1)                                                  \
    asm volatile("mma.sync.aligned.m16n8k16.row.col.f32.bf16.bf16.f32 "         \
                 "{%0,%1,%2,%3}, {%4,%5,%6,%7}, {%8,%9}, {%0,%1,%2,%3};"        \
                 : "+f"((c)[0]), "+f"((c)[1]), "+f"((c)[2]), "+f"((c)[3])       \
                 : "r"((a)[0]), "r"((a)[1]), "r"((a)[2]), "r"((a)[3]),          \
                   "r"(b0), "r"(b1))

__device__ __forceinline__ uint32_t packbf(__nv_bfloat16 a, __nv_bfloat16 b) {
    return (uint32_t)__bfloat16_as_ushort(a) | ((uint32_t)__bfloat16_as_ushort(b) << 16);
}

__device__ __forceinline__ void split2(float x0, float x1, uint32_t* p) {
    __nv_bfloat16 h0 = __float2bfloat16(x0);
    __nv_bfloat16 h1 = __float2bfloat16(x1);
    p[0] = packbf(h0, h1);
    float r0 = x0 - __bfloat162float(h0);
    float r1 = x1 - __bfloat162float(h1);
    p[1] = packbf(__float2bfloat16(r0), __float2bfloat16(r1));
}

// ======== prep: split fp32 arrays -> bf16 hi/lo (identical split2 math) ========
__global__ __launch_bounds__(256)
void split_all(const float* __restrict__ hidden, const float* __restrict__ Wq,
               const float* __restrict__ Wv,     const float* __restrict__ Wo,
               __nv_bfloat16* __restrict__ hh,  __nv_bfloat16* __restrict__ hl,
               __nv_bfloat16* __restrict__ wqh, __nv_bfloat16* __restrict__ wql,
               __nv_bfloat16* __restrict__ wvh, __nv_bfloat16* __restrict__ wvl,
               __nv_bfloat16* __restrict__ woh, __nv_bfloat16* __restrict__ wol)
{
    const size_t i4 = (size_t)blockIdx.x * 256 + threadIdx.x;  // float4 index
    const int which = blockIdx.y;
    const float* src; __nv_bfloat16 *dh, *dl; size_t n4;
    if (which == 0)      { src = hidden; dh = hh;  dl = hl;  n4 = (size_t)B_*S_*HID_/4; }
    else if (which == 1) { src = Wq;     dh = wqh; dl = wql; n4 = (size_t)NH_*HD_*HID_/4; }
    else if (which == 2) { src = Wv;     dh = wvh; dl = wvl; n4 = (size_t)NKV_*HD_*HID_/4; }
    else                 { src = Wo;     dh = woh; dl = wol; n4 = (size_t)HID_*NH_*HD_/4; }
    if (i4 >= n4) return;
    float4 v = ((const float4*)src)[i4];
    uint32_t p0[2], p1[2];
    split2(v.x, v.y, p0);
    split2(v.z, v.w, p1);
    ((uint2*)dh)[i4] = make_uint2(p0[0], p1[0]);
    ((uint2*)dl)[i4] = make_uint2(p0[1], p1[1]);
}

// ================= fp32 NT SGEMM (K projection — DO NOT ALTER OPS) ======
template<int MODE>
__global__ __launch_bounds__(256)
void gemm_nt(const float* __restrict__ A, const float* __restrict__ W,
             float* __restrict__ C, int M, int N, int K, int H)
{
    __shared__ float As[16][132];
    __shared__ float Bs[16][132];
    const int tid = threadIdx.x;
    const int tx = tid & 15, ty = tid >> 4;
    const int m0 = blockIdx.y * 128, n0 = blockIdx.x * 128;
    const int lr = tid >> 2;
    const int lk = (tid & 3) << 2;

    const float* Ap  = A + (size_t)(m0 + lr) * K + lk;
    const float* Ap2 = Ap + (size_t)64 * K;
    const float* Wp  = W + (size_t)(n0 + lr) * K + lk;
    const float* Wp2 = Wp + (size_t)64 * K;

    float acc[8][8];
#pragma unroll
    for (int i = 0; i < 8; i++)
#pragma unroll
        for (int j = 0; j < 8; j++) acc[i][j] = 0.f;

    for (int k0 = 0; k0 < K; k0 += 16) {
        float4 a0 = *(const float4*)(Ap  + k0);
        float4 a1 = *(const float4*)(Ap2 + k0);
        float4 w0 = *(const float4*)(Wp  + k0);
        float4 w1 = *(const float4*)(Wp2 + k0);
        __syncthreads();
        As[lk+0][lr]    = a0.x; As[lk+1][lr]    = a0.y; As[lk+2][lr]    = a0.z; As[lk+3][lr]    = a0.w;
        As[lk+0][lr+64] = a1.x; As[lk+1][lr+64] = a1.y; As[lk+2][lr+64] = a1.z; As[lk+3][lr+64] = a1.w;
        Bs[lk+0][lr]    = w0.x; Bs[lk+1][lr]    = w0.y; Bs[lk+2][lr]    = w0.z; Bs[lk+3][lr]    = w0.w;
        Bs[lk+0][lr+64] = w1.x; Bs[lk+1][lr+64] = w1.y; Bs[lk+2][lr+64] = w1.z; Bs[lk+3][lr+64] = w1.w;
        __syncthreads();
#pragma unroll
        for (int kk = 0; kk < 16; kk++) {
            float4 fa0 = *(const float4*)&As[kk][ty*4];
            float4 fa1 = *(const float4*)&As[kk][ty*4+64];
            float4 fb0 = *(const float4*)&Bs[kk][tx*4];
            float4 fb1 = *(const float4*)&Bs[kk][tx*4+64];
            float av[8] = {fa0.x,fa0.y,fa0.z,fa0.w, fa1.x,fa1.y,fa1.z,fa1.w};
            float bv[8] = {fb0.x,fb0.y,fb0.z,fb0.w, fb1.x,fb1.y,fb1.z,fb1.w};
#pragma unroll
            for (int i = 0; i < 8; i++)
#pragma unroll
                for (int j = 0; j < 8; j++) acc[i][j] += av[i]*bv[j];
        }
    }

#pragma unroll
    for (int i = 0; i < 8; i++) {
        int row = m0 + ty*4 + (i & 3) + (i >> 2) * 64;
#pragma unroll
        for (int jh = 0; jh < 2; jh++) {
            int col = n0 + tx*4 + jh*64;
            float4 vout = make_float4(acc[i][jh*4+0], acc[i][jh*4+1],
                                      acc[i][jh*4+2], acc[i][jh*4+3]);
            if (MODE == 0) {
                *(float4*)(C + (size_t)row * N + col) = vout;
            } else {
                int b = row >> 11, s = row & (S_-1);
                int h = col >> 8,  hd = col & (HD_-1);
                *(float4*)(C + (((size_t)(b*H + h) * S_ + s) * HD_ + hd)) = vout;
            }
        }
    }
}

// ======== 2-limb bf16 tensor GEMM, pre-split operands, k-tile 16 ========
// Double-buffered with register staging (16 regs), one sync/iter.
// Target: <=128 regs -> 2 CTAs/SM (regs were the occupancy limiter at k-tile 32).
// MMA sequence per accumulator identical to previous version -> bit-identical C.
template<int MODE>
__global__ __launch_bounds__(256, 2)
void gemm_pre(const __nv_bfloat16* __restrict__ Ah, const __nv_bfloat16* __restrict__ Al,
              const __nv_bfloat16* __restrict__ Bh, const __nv_bfloat16* __restrict__ Bl,
              float* __restrict__ C, int M, int N, int K, int H)
{
    extern __shared__ __nv_bfloat16 dsm[];
    // 2 buffers x 4 tiles [128][24] (16 k + 8 pad): buf*4 + {0:Ah,1:Al,2:Bh,3:Bl}
    auto tile = [&](int t) -> __nv_bfloat16 (*)[24] {
        return reinterpret_cast<__nv_bfloat16 (*)[24]>(dsm + (size_t)t * 128 * 24);
    };

    const int tid  = threadIdx.x;
    const int lane = tid & 31, wid = tid >> 5;
    const int wm = wid >> 2;
    const int wn = wid & 3;
    const int m0 = blockIdx.y * 128, n0 = blockIdx.x * 128;

    const int lr = tid >> 1;          // 0..127 row
    const int lc = (tid & 1) << 3;    // 0 or 8 (k offset, 16B granule)

    const __nv_bfloat16* pAh = Ah + (size_t)(m0 + lr) * K + lc;
    const __nv_bfloat16* pAl = Al + (size_t)(m0 + lr) * K + lc;
    const __nv_bfloat16* pBh = Bh + (size_t)(n0 + lr) * K + lc;
    const __nv_bfloat16* pBl = Bl + (size_t)(n0 + lr) * K + lc;

    float acc[4][4][4];
#pragma unroll
    for (int mt = 0; mt < 4; mt++)
#pragma unroll
        for (int nt = 0; nt < 4; nt++)
#pragma unroll
            for (int e = 0; e < 4; e++) acc[mt][nt][e] = 0.f;

    uint4 rah, ral, rbh, rbl;   // 16 staging regs
    auto load_tile = [&](int k0) {
        rah = *(const uint4*)(pAh + k0);
        ral = *(const uint4*)(pAl + k0);
        rbh = *(const uint4*)(pBh + k0);
        rbl = *(const uint4*)(pBl + k0);
    };
    auto store_tile = [&](int buf) {
        *(uint4*)&tile(buf*4 + 0)[lr][lc] = rah;
        *(uint4*)&tile(buf*4 + 1)[lr][lc] = ral;
        *(uint4*)&tile(buf*4 + 2)[lr][lc] = rbh;
        *(uint4*)&tile(buf*4 + 3)[lr][lc] = rbl;
    };

    load_tile(0);
    store_tile(0);
    __syncthreads();
    int cur = 0;

    for (int k0 = 0; k0 < K; k0 += 16) {
        const bool more = (k0 + 16 < K);
        if (more) load_tile(k0 + 16);

        // MMA on current buffer (single ks step of 16)
        {
            uint32_t Bf[2][2][4];
#pragma unroll
            for (int l = 0; l < 2; l++) {
#pragma unroll
                for (int g = 0; g < 2; g++) {
                    const int br = wn * 32 + g * 16 + (lane & 7) + ((lane >> 4) << 3);
                    const int bk = (((lane >> 3) & 1) << 3);
                    LDSM4(Bf[l][g], s2u(&tile(cur*4 + 2 + l)[br][bk]));
                }
            }
#pragma unroll
            for (int mt = 0; mt < 4; mt++) {
                uint32_t Af[2][4];
                const int ar = wm * 64 + mt * 16 + (lane & 15);
                const int ak = ((lane >> 4) << 3);
                LDSM4(Af[0], s2u(&tile(cur*4 + 0)[ar][ak]));
                LDSM4(Af[1], s2u(&tile(cur*4 + 1)[ar][ak]));
#pragma unroll
                for (int nt = 0; nt < 4; nt++) {
                    const int g = nt >> 1, p = (nt & 1) << 1;
                    float* c = acc[mt][nt];
                    MMA_BF16(c, Af[0], Bf[0][g][p], Bf[0][g][p+1]);   // hh
                    MMA_BF16(c, Af[1], Bf[0][g][p], Bf[0][g][p+1]);   // lh
                    MMA_BF16(c, Af[0], Bf[1][g][p], Bf[1][g][p+1]);   // hl
                }
            }
        }

        if (more) store_tile(cur ^ 1);
        __syncthreads();
        cur ^= 1;
    }

#pragma unroll
    for (int mt = 0; mt < 4; mt++) {
        const int row0 = m0 + wm * 64 + mt * 16 + (lane >> 2);
#pragma unroll
        for (int nt = 0; nt < 4; nt++) {
            const int col = n0 + wn * 32 + nt * 8 + ((lane & 3) << 1);
            float2 v0 = make_float2(acc[mt][nt][0], acc[mt][nt][1]);
            float2 v1 = make_float2(acc[mt][nt][2], acc[mt][nt][3]);
            if (MODE == 0) {
                *(float2*)(C + (size_t)row0       * N + col) = v0;
                *(float2*)(C + (size_t)(row0 + 8) * N + col) = v1;
            } else {
                const int h = col >> 8, hd = col & (HD_ - 1);
#pragma unroll
                for (int rr = 0; rr < 2; rr++) {
                    const int row = row0 + rr * 8;
                    const int b = row >> 11, s = row & (S_ - 1);
                    *(float2*)(C + (((size_t)(b * H + h) * S_ + s) * HD_ + hd)) =
                        rr ? v1 : v0;
                }
            }
        }
    }
}

// ---------------- RoPE on Q -> bf16 limbs ----------------
__global__ void rope_q_split(const float* __restrict__ q,
                             __nv_bfloat16* __restrict__ qh,
                             __nv_bfloat16* __restrict__ ql,
                             const float* __restrict__ cosp,
                             const float* __restrict__ sinp)
{
    size_t idx = (size_t)blockIdx.x * blockDim.x + threadIdx.x; // B*NH*S*128
    int d = (int)(idx & 127);
    size_t rrow = idx >> 7;
    int s = (int)(rrow & (S_-1));
    const float* row = q + rrow * HD_;
    float x1 = row[d], x2 = row[d + 128];
    float c1 = cosp[s*HD_ + d],       s1 = sinp[s*HD_ + d];
    float c2 = cosp[s*HD_ + d + 128], s2 = sinp[s*HD_ + d + 128];
    float v1 = x1 * c1 - x2 * s1;
    float v2 = x2 * c2 + x1 * s2;
    __nv_bfloat16 h1 = __float2bfloat16(v1);
    __nv_bfloat16 h2 = __float2bfloat16(v2);
    qh[rrow*HD_ + d]       = h1;
    qh[rrow*HD_ + d + 128] = h2;
    ql[rrow*HD_ + d]       = __float2bfloat16(v1 - __bfloat162float(h1));
    ql[rrow*HD_ + d + 128] = __float2bfloat16(v2 - __bfloat162float(h2));
}

// ------- RoPE + BFP quantize K -> exact bf16, s-major [B,NKV,S,HD] -------
__global__ __launch_bounds__(256)
void rope_quant_k(const float* __restrict__ k, __nv_bfloat16* __restrict__ kq,
                  const float* __restrict__ cosp, const float* __restrict__ sinp)
{
    int r = blockIdx.x;                 // (b*NKV+kv)*S + s
    int s = r & (S_-1);
    int d = threadIdx.x;
    const float* row = k + (size_t)r * HD_;
    float x = row[d];
    float other = (d < 128) ? -row[d + 128] : row[d - 128];
    float val = x * cosp[s*HD_ + d] + other * sinp[s*HD_ + d];

    __shared__ float red[256];
    red[d] = fabsf(val);
    __syncthreads();
    for (int off = 64; off > 0; off >>= 1) {
        if ((d & 127) < off) red[d] = fmaxf(red[d], red[d + off]);
        __syncthreads();
    }
    float maxabs = red[(d >> 7) << 7];

    float m = fmaxf(maxabs, 1e-30f);
    int ex;
    frexpf(m, &ex);
    float scale = ldexpf(1.0f, ex - 3);
    float qv = rintf(val / scale);
    qv = fminf(7.f, fmaxf(-7.f, qv)) * scale;
    if (!(maxabs > 0.f)) qv = 0.f;

    kq[(size_t)r * HD_ + d] = __float2bfloat16(qv);
}

// ------- V: fp32 [B,NKV,S,HD] -> bf16 limbs, transposed d-major [B,NKV,HD,S] -------
__global__ __launch_bounds__(256)
void v_split_t(const float* __restrict__ v,
               __nv_bfloat16* __restrict__ vh, __nv_bfloat16* __restrict__ vl)
{
    __shared__ float sm[64][65];
    const int s0 = blockIdx.x * 64, d0 = blockIdx.y * 64, bk = blockIdx.z;
    const int tid = threadIdx.x, lane = tid & 31, wid = tid >> 5;
    const float* base = v + ((size_t)bk * S_ + s0) * HD_ + d0;
    for (int i = tid; i < 64*16; i += 256) {
        int r = i >> 4, c = (i & 15) * 4;
        float4 t = *(const float4*)&base[(size_t)r * HD_ + c];
        sm[r][c] = t.x; sm[r][c+1] = t.y; sm[r][c+2] = t.z; sm[r][c+3] = t.w;
    }
    __syncthreads();
    for (int dr = wid; dr < 64; dr += 8) {
        float a  = sm[lane*2][dr];
        float b2 = sm[lane*2+1][dr];
        __nv_bfloat16 h0 = __float2bfloat16(a);
        __nv_bfloat16 h1 = __float2bfloat16(b2);
        uint32_t ph = packbf(h0, h1);
        uint32_t pl = packbf(__float2bfloat16(a  - __bfloat162float(h0)),
                             __float2bfloat16(b2 - __bfloat162float(h1)));
        size_t off = ((size_t)bk * HD_ + d0 + dr) * S_ + s0 + lane*2;
        *(uint32_t*)&vh[off] = ph;
        *(uint32_t*)&vl[off] = pl;
    }
}

// ---------------- tensor-core flash attention (causal, GQA) ----------------
// outputs O as bf16 limbs (hi/lo) directly -> feeds gemm_pre<0> without a prep pass.
__global__ __launch_bounds__(256)
void attn_mma(const __nv_bfloat16* __restrict__ qh, const __nv_bfloat16* __restrict__ ql,
              const __nv_bfloat16* __restrict__ kq,
              const __nv_bfloat16* __restrict__ vh, const __nv_bfloat16* __restrict__ vl,
              __nv_bfloat16* __restrict__ oh, __nv_bfloat16* __restrict__ ol)
{
    extern __shared__ __nv_bfloat16 smb[];
    __nv_bfloat16 (*Qhs)[264] = (__nv_bfloat16(*)[264])(smb);
    __nv_bfloat16 (*Qls)[264] = (__nv_bfloat16(*)[264])(smb + 64*264);
    __nv_bfloat16 (*Ks )[264] = (__nv_bfloat16(*)[264])(smb + 2*64*264);
    __nv_bfloat16 (*Vhs)[72]  = (__nv_bfloat16(*)[72]) (smb + 3*64*264);
    __nv_bfloat16 (*Vls)[72]  = (__nv_bfloat16(*)[72]) (smb + 3*64*264 + 256*72);
    __nv_bfloat16 (*Phs)[72]  = (__nv_bfloat16(*)[72]) (smb + 3*64*264 + 2*256*72);
    __nv_bfloat16 (*Pls)[72]  = (__nv_bfloat16(*)[72]) (smb + 3*64*264 + 2*256*72 + 64*72);
    float* scorr = (float*)(smb + 3*64*264 + 2*256*72 + 2*64*72);

    const int iq = blockIdx.x, h = blockIdx.y, b = blockIdx.z;
    const int kvb = b * NKV_ + (h >> 1);          // NREP_ = 2
    const int tid = threadIdx.x, lane = tid & 31, wid = tid >> 5;

    const size_t qrow0 = ((size_t)(b*NH_ + h) * S_ + (size_t)iq * 64);
    for (int i = tid; i < 64*32; i += 256) {
        int r = i >> 5, c = (i & 31) * 8;
        *(uint4*)&Qhs[r][c] = *(const uint4*)&qh[(qrow0 + r) * HD_ + c];
        *(uint4*)&Qls[r][c] = *(const uint4*)&ql[(qrow0 + r) * HD_ + c];
    }

    float oc[16][4];
#pragma unroll
    for (int t = 0; t < 16; t++)
#pragma unroll
        for (int e = 0; e < 4; e++) oc[t][e] = 0.f;
    float mrun[2] = {-1e30f, -1e30f};
    float lrun[2] = {0.f, 0.f};

    for (int j = 0; j <= iq; j++) {
        const int k0 = j * 64;
        __syncthreads();
        for (int i = tid; i < 64*32; i += 256) {
            int r = i >> 5, c = (i & 31) * 8;
            *(uint4*)&Ks[r][c] = *(const uint4*)&kq[((size_t)kvb * S_ + k0 + r) * HD_ + c];
        }
        for (int i = tid; i < 256*8; i += 256) {
            int r = i >> 3, c = (i & 7) * 8;
            *(uint4*)&Vhs[r][c] = *(const uint4*)&vh[((size_t)kvb * HD_ + r) * S_ + k0 + c];
            *(uint4*)&Vls[r][c] = *(const uint4*)&vl[((size_t)kvb * HD_ + r) * S_ + k0 + c];
        }
        __syncthreads();

        if (wid < 4) {
            const int qb = wid * 16;
            float sc[8][4];
#pragma unroll
            for (int t = 0; t < 8; t++)
#pragma unroll
                for (int e = 0; e < 4; e++) sc[t][e] = 0.f;

            for (int ks = 0; ks < 256; ks += 16) {
                uint32_t Ah[4], Al[4];
                const int ar = qb + (lane & 15);
                const int ak = ks + ((lane >> 4) << 3);
                LDSM4(Ah, s2u(&Qhs[ar][ak]));
                LDSM4(Al, s2u(&Qls[ar][ak]));
                uint32_t Bk[4][4];
#pragma unroll
                for (int g = 0; g < 4; g++) {
                    const int br = g*16 + (lane & 7) + ((lane >> 4) << 3);
                    const int bk = ks + (((lane >> 3) & 1) << 3);
                    LDSM4(Bk[g], s2u(&Ks[br][bk]));
                }
#pragma unroll
                for (int t = 0; t < 8; t++) {
                    const int g = t >> 1, p = (t & 1) << 1;
                    MMA_BF16(sc[t], Ah, Bk[g][p], Bk[g][p+1]);
                    MMA_BF16(sc[t], Al, Bk[g][p], Bk[g][p+1]);
                }
            }

            const bool diag = (j == iq);
            const int r0 = lane >> 2;
#pragma unroll
            for (int rr = 0; rr < 2; rr++) {
                const int rloc = qb + r0 + rr*8;
                const int rg = iq*64 + rloc;
                float mx = -1e30f;
#pragma unroll
                for (int t = 0; t < 8; t++) {
#pragma unroll
                    for (int e = 0; e < 2; e++) {
                        float sv = sc[t][rr*2 + e] * 0.0625f;
                        const int cg = k0 + t*8 + (lane & 3)*2 + e;
                        if (diag && cg > rg) sv = -1e30f;
                        sc[t][rr*2 + e] = sv;
                        mx = fmaxf(mx, sv);
                    }
                }
                mx = fmaxf(mx, __shfl_xor_sync(0xffffffffu, mx, 1));
                mx = fmaxf(mx, __shfl_xor_sync(0xffffffffu, mx, 2));
                const float mnew = fmaxf(mrun[rr], mx);
                const float corr = __expf(mrun[rr] - mnew);
                mrun[rr] = mnew;
                float ls = 0.f;
#pragma unroll
                for (int t = 0; t < 8; t++) {
                    float p0 = __expf(sc[t][rr*2 + 0] - mnew);
                    float p1 = __expf(sc[t][rr*2 + 1] - mnew);
                    ls += p0 + p1;
                    __nv_bfloat16 h0 = __float2bfloat16(p0);
                    __nv_bfloat16 h1 = __float2bfloat16(p1);
                    const int col = t*8 + (lane & 3)*2;
                    *(uint32_t*)&Phs[rloc][col] = packbf(h0, h1);
                    *(uint32_t*)&Pls[rloc][col] =
                        packbf(__float2bfloat16(p0 - __bfloat162float(h0)),
                               __float2bfloat16(p1 - __bfloat162float(h1)));
                }
                ls += __shfl_xor_sync(0xffffffffu, ls, 1);
                ls += __shfl_xor_sync(0xffffffffu, ls, 2);
                lrun[rr] = lrun[rr] * corr + ls;
                if ((lane & 3) == 0) scorr[rloc] = corr;
            }
        }
        __syncthreads();

        {
            const int qb = (wid & 3) * 16, db = (wid >> 2) * 128;
            const float c0 = scorr[qb + (lane >> 2)];
            const float c1 = scorr[qb + (lane >> 2) + 8];
#pragma unroll
            for (int t = 0; t < 16; t++) {
                oc[t][0] *= c0; oc[t][1] *= c0;
                oc[t][2] *= c1; oc[t][3] *= c1;
            }
#pragma unroll
            for (int kk = 0; kk < 64; kk += 16) {
                uint32_t Aph[4], Apl[4];
                const int ar = qb + (lane & 15);
                const int ak = kk + ((lane >> 4) << 3);
                LDSM4(Aph, s2u(&Phs[ar][ak]));
                LDSM4(Apl, s2u(&Pls[ar][ak]));
#pragma unroll
                for (int g = 0; g < 8; g++) {
                    uint32_t Bvh[4], Bvl[4];
                    const int vr = db + g*16 + (lane & 7) + ((lane >> 4) << 3);
                    const int vc = kk + (((lane >> 3) & 1) << 3);
                    LDSM4(Bvh, s2u(&Vhs[vr][vc]));
                    LDSM4(Bvl, s2u(&Vls[vr][vc]));
#pragma unroll
                    for (int tt = 0; tt < 2; tt++) {
                        const int t = g*2 + tt, p = tt << 1;
                        MMA_BF16(oc[t], Aph, Bvh[p], Bvh[p+1]);
                        MMA_BF16(oc[t], Apl, Bvh[p], Bvh[p+1]);
                        MMA_BF16(oc[t], Aph, Bvl[p], Bvl[p+1]);
                    }
                }
            }
        }
    }

    __syncthreads();
    if (wid < 4 && (lane & 3) == 0) {
        scorr[wid*16 + (lane >> 2)]     = 1.f / lrun[0];
        scorr[wid*16 + (lane >> 2) + 8] = 1.f / lrun[1];
    }
    __syncthreads();

    {
        const int qb = (wid & 3) * 16, db = (wid >> 2) * 128;
        const float i0 = scorr[qb + (lane >> 2)];
        const float i1 = scorr[qb + (lane >> 2) + 8];
        const int r0g = iq*64 + qb + (lane >> 2);
#pragma unroll
        for (int t = 0; t < 16; t++) {
            const int col = db + t*8 + (lane & 3)*2;
            const size_t off0 = ((size_t)b*S_ + r0g    ) * (NH_*HD_) + (size_t)h*HD_ + col;
            const size_t off1 = ((size_t)b*S_ + r0g + 8) * (NH_*HD_) + (size_t)h*HD_ + col;
            uint32_t p0[2], p1[2];
            split2(oc[t][0]*i0, oc[t][1]*i0, p0);
            split2(oc[t][2]*i1, oc[t][3]*i1, p1);
            *(uint32_t*)&oh[off0] = p0[0];
            *(uint32_t*)&ol[off0] = p0[1];
            *(uint32_t*)&oh[off1] = p1[0];
            *(uint32_t*)&ol[off1] = p1[1];
        }
    }
}

// ---------------- launcher ----------------
extern "C" void kernel_launch(void* const* d_in, const int* in_sizes, int n_in,
                              void* d_out, int out_size)
{
    const float* hidden = (const float*)d_in[0];
    const float* Wq     = (const float*)d_in[1];
    const float* Wk     = (const float*)d_in[2];
    const float* Wv     = (const float*)d_in[3];
    const float* Wo     = (const float*)d_in[4];
    const float* cosp   = (const float*)d_in[5];
    const float* sinp   = (const float*)d_in[6];
    float* out = (float*)d_out;
    (void)in_sizes; (void)n_in; (void)out_size;

    float *q, *k, *vv;
    __nv_bfloat16 *qhp, *qlp, *kqp, *vhp, *vlp;
    __nv_bfloat16 *hh, *hl, *wqh, *wql, *wvh, *wvl, *woh, *wol, *ohp, *olp;
    cudaGetSymbolAddress((void**)&q,   g_q);
    cudaGetSymbolAddress((void**)&k,   g_k);
    cudaGetSymbolAddress((void**)&vv,  g_v);
    cudaGetSymbolAddress((void**)&qhp, g_qh);
    cudaGetSymbolAddress((void**)&qlp, g_ql);
    cudaGetSymbolAddress((void**)&kqp, g_kq);
    cudaGetSymbolAddress((void**)&vhp, g_vh);
    cudaGetSymbolAddress((void**)&vlp, g_vl);
    cudaGetSymbolAddress((void**)&hh,  g_hh);
    cudaGetSymbolAddress((void**)&hl,  g_hl);
    cudaGetSymbolAddress((void**)&wqh, g_wqh);
    cudaGetSymbolAddress((void**)&wql, g_wql);
    cudaGetSymbolAddress((void**)&wvh, g_wvh);
    cudaGetSymbolAddress((void**)&wvl, g_wvl);
    cudaGetSymbolAddress((void**)&woh, g_woh);
    cudaGetSymbolAddress((void**)&wol, g_wol);
    cudaGetSymbolAddress((void**)&ohp, g_oh);
    cudaGetSymbolAddress((void**)&olp, g_ol);

    const int M = B_ * S_;  // 4096
    dim3 blk(256);

    const int smemG = 2 * 4 * 128 * 24 * (int)sizeof(__nv_bfloat16);  // 49152
    cudaFuncSetAttribute(gemm_pre<1>, cudaFuncAttributeMaxDynamicSharedMemorySize, smemG);
    cudaFuncSetAttribute(gemm_pre<0>, cudaFuncAttributeMaxDynamicSharedMemorySize, smemG);

    // pre-split hidden / Wq / Wv / Wo into bf16 limbs (identical split2 math)
    split_all<<<dim3(12288, 4), blk>>>(hidden, Wq, Wv, Wo,
                                       hh, hl, wqh, wql, wvh, wvl, woh, wol);

    // Q projection: tensor 2-limb on pre-split operands
    gemm_pre<1><<<dim3((NH_*HD_)/128,  M/128), blk, smemG>>>(hh, hl, wqh, wql, q,  M, NH_*HD_,  HID_, NH_);
    // K projection: fp32 FFMA (byte-identical path into the BFP quantizer)
    gemm_nt<1><<<dim3((NKV_*HD_)/128, M/128), blk>>>(hidden, Wk, k, M, NKV_*HD_, HID_, NKV_);
    // V projection: tensor 2-limb on pre-split operands
    gemm_pre<1><<<dim3((NKV_*HD_)/128, M/128), blk, smemG>>>(hh, hl, wvh, wvl, vv, M, NKV_*HD_, HID_, NKV_);

    rope_q_split<<<(B_*NH_*S_*128)/256, 256>>>(q, qhp, qlp, cosp, sinp);
    rope_quant_k<<<B_*NKV_*S_, 256>>>(k, kqp, cosp, sinp);
    v_split_t<<<dim3(S_/64, HD_/64, B_*NKV_), 256>>>(vv, vhp, vlp);

    const int smemA = (3*64*264 + 2*256*72 + 2*64*72) * (int)sizeof(__nv_bfloat16) + 64*(int)sizeof(float);
    cudaFuncSetAttribute(attn_mma, cudaFuncAttributeMaxDynamicSharedMemorySize, smemA);
    attn_mma<<<dim3(S_/64, NH_, B_), 256, smemA>>>(qhp, qlp, kqp, vhp, vlp, ohp, olp);

    // output projection: tensor 2-limb, A limbs come straight from attention epilogue
    gemm_pre<0><<<dim3(HID_/128, M/128), blk, smemG>>>(ohp, olp, woh, wol, out, M, HID_, NH_*HD_, 0);
}